// round 6
// baseline (speedup 1.0000x reference)
#include <cuda_runtime.h>
#include <math.h>

#define B_   128
#define T_   2048
#define O_   128
#define E_   512
#define L_   34
#define NG   512
#define KSPL 12           // 12 segment-uniform K-slabs of 64
#define KPER 64
#define BM_G 32
#define BN_G 64
#define SCH  8
#define TCH  (T_ / SCH)   // 256

// d_out layout: out[128*34] | c[128*128] | sh[128*128] | sc[128*128]
#define OUT_OFF_C   (B_ * L_)
#define OUT_OFF_SH  (OUT_OFF_C + B_ * O_)
#define OUT_OFF_SC  (OUT_OFF_SH + B_ * O_)

// ---------------- device scratch ----------------
__device__ __align__(16) float g_part[KSPL][B_ * NG];
__device__ int   g_len[B_];
__device__ float g_pm[B_ * SCH];
__device__ float g_pr[B_ * SCH];
__device__ __align__(16) float g_pacc[B_ * SCH * O_];
__device__ int   g_cnt[B_];   // zero-init; self-resetting ticket

#define N_GEMM_BLK ((B_ / BM_G) * (NG / BN_G) * KSPL)   // 4*8*12 = 384

// ---------------- launch 1: single-shot split-K GEMM + len ----------------
__global__ void __launch_bounds__(256)
gemm_len_kernel(const float* __restrict__ y1, const float* __restrict__ c1,
                const float* __restrict__ sh1,
                const float* __restrict__ Wih, const float* __restrict__ Whh,
                const float* __restrict__ mask) {
    __shared__ float As[BM_G][68];        // [m][k]
    __shared__ float Bs[KPER][BN_G + 4];  // [k][n]
    int bid = blockIdx.x;
    int tid = threadIdx.x;

    if (bid >= N_GEMM_BLK) {
        // ---- length path (reuse As as scratch) ----
        float* s = &As[0][0];
        int b = bid - N_GEMM_BLK;
        int lane = tid & 31, warp = tid >> 5;
        const float4* m4 = (const float4*)(mask + (size_t)b * T_);
        float acc = 0.f;
        for (int i = tid; i < T_ / 4; i += 256) {
            float4 v = m4[i];
            acc += v.x + v.y + v.z + v.w;
        }
#pragma unroll
        for (int off = 16; off; off >>= 1) acc += __shfl_xor_sync(0xffffffffu, acc, off);
        if (lane == 0) s[warp] = acc;
        __syncthreads();
        if (tid == 0) {
            float t = 0.f;
            for (int w = 0; w < 8; w++) t += s[w];
            g_len[b] = (int)(t + 0.5f);
        }
        return;
    }

    // ---- gemm path: one K-slab, no inner syncs ----
    int ks = bid >> 5;                    // 0..11
    int rem = bid & 31;
    int m0 = (rem >> 3) * BM_G;           // 0,32,64,96
    int n0 = (rem & 7) * BN_G;            // 0..448
    int k0 = ks * KPER;                   // segment-uniform

    const float* xbase; int xstride;
    if (k0 < E_)            { xbase = y1  + k0;             xstride = E_; }
    else if (k0 < E_ + O_)  { xbase = c1  + (k0 - E_);      xstride = O_; }
    else                    { xbase = sh1 + (k0 - E_ - O_); xstride = O_; }
    const float* wbase; int wstride;
    if (k0 < E_ + O_) { wbase = Wih + k0;             wstride = E_ + O_; }
    else              { wbase = Whh + (k0 - E_ - O_); wstride = O_; }

    // load A: 32 rows x 64 k; thread -> row=tid>>3, kc=(tid&7)*4; two chunks kc, kc+32
    {
        int row = tid >> 3, kc = (tid & 7) * 4;
        const float* ap = xbase + (size_t)(m0 + row) * xstride + kc;
        float4 a0 = *(const float4*)ap;
        float4 a1 = *(const float4*)(ap + 32);
        *(float4*)&As[row][kc]      = a0;
        *(float4*)&As[row][kc + 32] = a1;
    }
    // load B transposed: 64 rows(n) x 64 k; thread -> n=tid>>2, kc=(tid&3)*16
    {
        int n = tid >> 2, kc = (tid & 3) * 16;
        const float* bp = wbase + (size_t)(n0 + n) * wstride + kc;
        float4 w0 = *(const float4*)bp;
        float4 w1 = *(const float4*)(bp + 4);
        float4 w2 = *(const float4*)(bp + 8);
        float4 w3 = *(const float4*)(bp + 12);
        Bs[kc + 0][n] = w0.x;  Bs[kc + 1][n] = w0.y;  Bs[kc + 2][n] = w0.z;  Bs[kc + 3][n] = w0.w;
        Bs[kc + 4][n] = w1.x;  Bs[kc + 5][n] = w1.y;  Bs[kc + 6][n] = w1.z;  Bs[kc + 7][n] = w1.w;
        Bs[kc + 8][n] = w2.x;  Bs[kc + 9][n] = w2.y;  Bs[kc + 10][n] = w2.z; Bs[kc + 11][n] = w2.w;
        Bs[kc + 12][n] = w3.x; Bs[kc + 13][n] = w3.y; Bs[kc + 14][n] = w3.z; Bs[kc + 15][n] = w3.w;
    }
    __syncthreads();

    int tm = (tid >> 4) * 2;   // 0..30
    int tn = (tid & 15) * 4;   // 0..60
    float c0[4] = {0.f, 0.f, 0.f, 0.f};
    float c1r[4] = {0.f, 0.f, 0.f, 0.f};
#pragma unroll 8
    for (int k = 0; k < KPER; k++) {
        float a0 = As[tm][k], a1 = As[tm + 1][k];
        float4 bv = *(const float4*)&Bs[k][tn];
        c0[0] += a0 * bv.x; c0[1] += a0 * bv.y; c0[2] += a0 * bv.z; c0[3] += a0 * bv.w;
        c1r[0] += a1 * bv.x; c1r[1] += a1 * bv.y; c1r[2] += a1 * bv.z; c1r[3] += a1 * bv.w;
    }
    float* P = g_part[ks];
    *(float4*)&P[(m0 + tm) * NG + n0 + tn]     = make_float4(c0[0], c0[1], c0[2], c0[3]);
    *(float4*)&P[(m0 + tm + 1) * NG + n0 + tn] = make_float4(c1r[0], c1r[1], c1r[2], c1r[3]);
}

// ---------------- attention group body ----------------
__device__ __forceinline__ float sigf(float x) { return 1.f / (1.f + __expf(-x)); }

template <bool FULL>
__device__ __forceinline__ void attn_group(const float4* __restrict__ hk4,
                                           const float4* __restrict__ hv4,
                                           int t, int len, float4 q, int lane,
                                           float& m, float& r, float4& acc) {
    int b0 = t * (O_ / 4);
    // k loads first
    float4 k0 = hk4[b0 + lane];
    float4 k1 = hk4[b0 + 32 + lane];
    float4 k2 = hk4[b0 + 64 + lane];
    float4 k3 = hk4[b0 + 96 + lane];
    float d0 = k0.x * q.x + k0.y * q.y + k0.z * q.z + k0.w * q.w;
    float d1 = k1.x * q.x + k1.y * q.y + k1.z * q.z + k1.w * q.w;
    float d2 = k2.x * q.x + k2.y * q.y + k2.z * q.z + k2.w * q.w;
    float d3 = k3.x * q.x + k3.y * q.y + k3.z * q.z + k3.w * q.w;
    // v loads issued before shfl chain: latency overlaps the serial reduce
    float4 v0 = hv4[b0 + lane];
    float4 v1 = hv4[b0 + 32 + lane];
    float4 v2 = hv4[b0 + 64 + lane];
    float4 v3 = hv4[b0 + 96 + lane];
#pragma unroll
    for (int off = 16; off; off >>= 1) {
        d0 += __shfl_xor_sync(0xffffffffu, d0, off);
        d1 += __shfl_xor_sync(0xffffffffu, d1, off);
        d2 += __shfl_xor_sync(0xffffffffu, d2, off);
        d3 += __shfl_xor_sync(0xffffffffu, d3, off);
    }
    if (!FULL) {
        d1 = (t + 1 < len) ? d1 : -INFINITY;
        d2 = (t + 2 < len) ? d2 : -INFINITY;
        d3 = (t + 3 < len) ? d3 : -INFINITY;
    }
    float g = fmaxf(fmaxf(d0, d1), fmaxf(d2, d3));
    float nm = fmaxf(m, g);
    float e0 = __expf(d0 - nm);
    float e1 = __expf(d1 - nm);
    float e2 = __expf(d2 - nm);
    float e3 = __expf(d3 - nm);
    float scale = __expf(m - nm);
    acc.x = acc.x * scale + e0 * v0.x + e1 * v1.x + e2 * v2.x + e3 * v3.x;
    acc.y = acc.y * scale + e0 * v0.y + e1 * v1.y + e2 * v2.y + e3 * v3.y;
    acc.z = acc.z * scale + e0 * v0.z + e1 * v1.z + e2 * v2.z + e3 * v3.z;
    acc.w = acc.w * scale + e0 * v0.w + e1 * v1.w + e2 * v2.w + e3 * v3.w;
    r = r * scale + (e0 + e1 + e2 + e3);
    m = nm;
}

// ---------------- launch 2: act (from partials) + attention + fused combine/MLP ----------------
__global__ void __launch_bounds__(256, 6)
attn_kernel(const float* __restrict__ hk, const float* __restrict__ hv,
            const float* __restrict__ sc1,
            const float* __restrict__ bih, const float* __restrict__ bhh,
            float* __restrict__ dout,
            const float* __restrict__ W1, const float* __restrict__ b1,
            const float* __restrict__ W2, const float* __restrict__ b2,
            const float* __restrict__ W3, const float* __restrict__ b3) {
    __shared__ __align__(16) float s_q[O_];    // sc (attention query)
    __shared__ float s_sh[O_];
    __shared__ float s_m[8], s_r[8];
    __shared__ float s_acc[8][O_];
    __shared__ int s_last;
    int b = blockIdx.y;
    int chunk = blockIdx.x;
    int tid = threadIdx.x;
    int warp = tid >> 5, lane = tid & 31;

    // ---- startup: compute this row's LSTM activations from split-K partials ----
    if (tid < O_) {
        int o = tid;
        float g4[4];
#pragma unroll
        for (int gi = 0; gi < 4; gi++) {
            int n = gi * O_ + o;
            float v = bih[n] + bhh[n];
#pragma unroll
            for (int ks = 0; ks < KSPL; ks++) v += g_part[ks][b * NG + n];
            g4[gi] = v;
        }
        float sc = sigf(g4[1]) * sc1[b * O_ + o] + sigf(g4[0]) * tanhf(g4[2]);
        float sh = sigf(g4[3]) * tanhf(sc);
        s_q[o] = sc;
        s_sh[o] = sh;
        if (chunk == 0) {
            dout[OUT_OFF_SC + b * O_ + o] = sc;
            dout[OUT_OFF_SH + b * O_ + o] = sh;
        }
    }
    __syncthreads();

    float4 q = ((const float4*)s_q)[lane];
    const float4* hk4 = (const float4*)(hk) + (size_t)b * T_ * (O_ / 4);
    const float4* hv4 = (const float4*)(hv) + (size_t)b * T_ * (O_ / 4);

    int len = g_len[b];
    int t0 = chunk * TCH + warp * 32;
    int v = len - t0;

    float m = -INFINITY, r = 0.f;
    float4 acc = make_float4(0.f, 0.f, 0.f, 0.f);

    if (v >= 32) {
#pragma unroll 2
        for (int i = 0; i < 32; i += 4)
            attn_group<true>(hk4, hv4, t0 + i, len, q, lane, m, r, acc);
    } else if (v > 0) {
        for (int i = 0; i < v; i += 4)
            attn_group<false>(hk4, hv4, t0 + i, len, q, lane, m, r, acc);
    }

    s_acc[warp][4 * lane + 0] = acc.x;
    s_acc[warp][4 * lane + 1] = acc.y;
    s_acc[warp][4 * lane + 2] = acc.z;
    s_acc[warp][4 * lane + 3] = acc.w;
    if (lane == 0) { s_m[warp] = m; s_r[warp] = r; }
    __syncthreads();

    if (tid < O_) {
        float M = -INFINITY;
#pragma unroll
        for (int w = 0; w < 8; w++) if (s_r[w] > 0.f) M = fmaxf(M, s_m[w]);
        float R = 0.f, A = 0.f;
#pragma unroll
        for (int w = 0; w < 8; w++) {
            if (s_r[w] > 0.f) {
                float f = __expf(s_m[w] - M);
                R += s_r[w] * f;
                A += s_acc[w][tid] * f;
            }
        }
        int p = b * SCH + chunk;
        g_pacc[p * O_ + tid] = A;
        if (tid == 0) { g_pm[p] = M; g_pr[p] = R; }
    }
    __syncthreads();

    if (tid == 0) {
        __threadfence();
        int old = atomicAdd(&g_cnt[b], 1);
        if (old == SCH - 1) { g_cnt[b] = 0; s_last = 1; } else { s_last = 0; }
    }
    __syncthreads();
    if (!s_last) return;
    __threadfence();

    // ---- fused combine -> c, then MLP + softmax ----
    __shared__ float cs[O_], h[L_], z[L_];
    __shared__ float sM, sZ;
    if (tid == 0) {
        float M = -INFINITY;
        for (int s = 0; s < SCH; s++) if (g_pr[b * SCH + s] > 0.f) M = fmaxf(M, g_pm[b * SCH + s]);
        float Z = 0.f;
        for (int s = 0; s < SCH; s++)
            if (g_pr[b * SCH + s] > 0.f) Z += g_pr[b * SCH + s] * __expf(g_pm[b * SCH + s] - M);
        sM = M; sZ = Z;
    }
    __syncthreads();
    if (tid < O_) {
        float A = 0.f;
#pragma unroll
        for (int s = 0; s < SCH; s++) {
            if (g_pr[b * SCH + s] > 0.f)
                A += g_pacc[(b * SCH + s) * O_ + tid] * __expf(g_pm[b * SCH + s] - sM);
        }
        float cval = A / sZ;
        cs[tid] = cval;
        dout[OUT_OFF_C + b * O_ + tid] = cval;
    }
    __syncthreads();
    if (tid < L_) {
        float a = b1[tid] + b2[tid];
        const float* w1 = &W1[tid * O_];
        const float* w2 = &W2[tid * O_];
#pragma unroll 4
        for (int k = 0; k < O_; k++) a += s_sh[k] * w1[k] + cs[k] * w2[k];
        h[tid] = fmaxf(a, 0.f);
    }
    __syncthreads();
    if (tid < L_) {
        float a = b3[tid];
        const float* w3 = &W3[tid * L_];
#pragma unroll
        for (int j = 0; j < L_; j++) a += h[j] * w3[j];
        z[tid] = a;
    }
    __syncthreads();
    if (tid == 0) {
        float M = -INFINITY;
        for (int j = 0; j < L_; j++) M = fmaxf(M, z[j]);
        float S = 0.f;
        for (int j = 0; j < L_; j++) { float e = __expf(z[j] - M); z[j] = e; S += e; }
        float inv = 1.f / S;
        for (int j = 0; j < L_; j++) dout[b * L_ + j] = z[j] * inv;
    }
}

// ---------------- launcher ----------------
extern "C" void kernel_launch(void* const* d_in, const int* in_sizes, int n_in,
                              void* d_out, int out_size) {
    const float* P[17];
    if (n_in >= 17 && in_sizes[0] == B_ * T_ * O_) {
        for (int i = 0; i < 17; i++) P[i] = (const float*)d_in[i];
    } else {
        P[0]  = (const float*)d_in[11];  // hk
        P[1]  = (const float*)d_in[12];  // hv
        P[2]  = (const float*)d_in[16];  // y_1
        P[3]  = (const float*)d_in[10];  // c_1
        P[4]  = (const float*)d_in[15];  // sh_1
        P[5]  = (const float*)d_in[14];  // sc_1
        P[6]  = (const float*)d_in[13];  // mask
        P[7]  = (const float*)d_in[4];   // W_ih
        P[8]  = (const float*)d_in[9];   // b_ih
        P[9]  = (const float*)d_in[3];   // W_hh
        P[10] = (const float*)d_in[8];   // b_hh
        P[11] = (const float*)d_in[0];   // W1
        P[12] = (const float*)d_in[5];   // b1
        P[13] = (const float*)d_in[1];   // W2
        P[14] = (const float*)d_in[6];   // b2
        P[15] = (const float*)d_in[2];   // W3
        P[16] = (const float*)d_in[7];   // b3
    }
    const float *hk = P[0], *hv = P[1], *y1 = P[2], *c1 = P[3], *sh1 = P[4], *sc1 = P[5];
    const float *mask = P[6], *Wih = P[7], *bih = P[8], *Whh = P[9], *bhh = P[10];
    const float *W1 = P[11], *b1 = P[12], *W2 = P[13], *b2 = P[14], *W3 = P[15], *b3 = P[16];
    float* dout = (float*)d_out;

    gemm_len_kernel<<<N_GEMM_BLK + B_, 256>>>(y1, c1, sh1, Wih, Whh, mask);
    attn_kernel<<<dim3(SCH, B_), 256>>>(hk, hv, sc1, bih, bhh, dout,
                                        W1, b1, W2, b2, W3, b3);
}

// round 7
// speedup vs baseline: 1.1689x; 1.1689x over previous
#include <cuda_runtime.h>
#include <math.h>

#define B_   128
#define T_   2048
#define O_   128
#define E_   512
#define L_   34
#define NG   512
#define KSPL 12           // 12 segment-uniform K-slabs of 64
#define KPER 64
#define BM_G 32
#define BN_G 64
#define SCH  8
#define TCH  (T_ / SCH)   // 256

// d_out layout: out[128*34] | c[128*128] | sh[128*128] | sc[128*128]
#define OUT_OFF_C   (B_ * L_)
#define OUT_OFF_SH  (OUT_OFF_C + B_ * O_)
#define OUT_OFF_SC  (OUT_OFF_SH + B_ * O_)

// ---------------- device scratch ----------------
__device__ __align__(16) float g_part[KSPL][B_ * NG];
__device__ int   g_len[B_];
__device__ float g_pm[B_ * SCH];
__device__ float g_pr[B_ * SCH];
__device__ __align__(16) float g_pacc[B_ * SCH * O_];

#define N_GEMM_BLK ((B_ / BM_G) * (NG / BN_G) * KSPL)   // 4*8*12 = 384

// ---------------- launch 1: single-shot split-K GEMM + len (R6, measured ~1us) ----------------
__global__ void __launch_bounds__(256)
gemm_len_kernel(const float* __restrict__ y1, const float* __restrict__ c1,
                const float* __restrict__ sh1,
                const float* __restrict__ Wih, const float* __restrict__ Whh,
                const float* __restrict__ mask) {
    __shared__ float As[BM_G][68];        // [m][k]
    __shared__ float Bs[KPER][BN_G + 4];  // [k][n]
    int bid = blockIdx.x;
    int tid = threadIdx.x;

    if (bid >= N_GEMM_BLK) {
        // ---- length path ----
        float* s = &As[0][0];
        int b = bid - N_GEMM_BLK;
        int lane = tid & 31, warp = tid >> 5;
        const float4* m4 = (const float4*)(mask + (size_t)b * T_);
        float acc = 0.f;
        for (int i = tid; i < T_ / 4; i += 256) {
            float4 v = m4[i];
            acc += v.x + v.y + v.z + v.w;
        }
#pragma unroll
        for (int off = 16; off; off >>= 1) acc += __shfl_xor_sync(0xffffffffu, acc, off);
        if (lane == 0) s[warp] = acc;
        __syncthreads();
        if (tid == 0) {
            float t = 0.f;
            for (int w = 0; w < 8; w++) t += s[w];
            g_len[b] = (int)(t + 0.5f);
        }
        return;
    }

    // ---- gemm path: one K-slab, no inner syncs ----
    int ks = bid >> 5;                    // 0..11
    int rem = bid & 31;
    int m0 = (rem >> 3) * BM_G;
    int n0 = (rem & 7) * BN_G;
    int k0 = ks * KPER;                   // segment-uniform

    const float* xbase; int xstride;
    if (k0 < E_)            { xbase = y1  + k0;             xstride = E_; }
    else if (k0 < E_ + O_)  { xbase = c1  + (k0 - E_);      xstride = O_; }
    else                    { xbase = sh1 + (k0 - E_ - O_); xstride = O_; }
    const float* wbase; int wstride;
    if (k0 < E_ + O_) { wbase = Wih + k0;             wstride = E_ + O_; }
    else              { wbase = Whh + (k0 - E_ - O_); wstride = O_; }

    {
        int row = tid >> 3, kc = (tid & 7) * 4;
        const float* ap = xbase + (size_t)(m0 + row) * xstride + kc;
        float4 a0 = *(const float4*)ap;
        float4 a1 = *(const float4*)(ap + 32);
        *(float4*)&As[row][kc]      = a0;
        *(float4*)&As[row][kc + 32] = a1;
    }
    {
        int n = tid >> 2, kc = (tid & 3) * 16;
        const float* bp = wbase + (size_t)(n0 + n) * wstride + kc;
        float4 w0 = *(const float4*)bp;
        float4 w1 = *(const float4*)(bp + 4);
        float4 w2 = *(const float4*)(bp + 8);
        float4 w3 = *(const float4*)(bp + 12);
        Bs[kc + 0][n] = w0.x;  Bs[kc + 1][n] = w0.y;  Bs[kc + 2][n] = w0.z;  Bs[kc + 3][n] = w0.w;
        Bs[kc + 4][n] = w1.x;  Bs[kc + 5][n] = w1.y;  Bs[kc + 6][n] = w1.z;  Bs[kc + 7][n] = w1.w;
        Bs[kc + 8][n] = w2.x;  Bs[kc + 9][n] = w2.y;  Bs[kc + 10][n] = w2.z; Bs[kc + 11][n] = w2.w;
        Bs[kc + 12][n] = w3.x; Bs[kc + 13][n] = w3.y; Bs[kc + 14][n] = w3.z; Bs[kc + 15][n] = w3.w;
    }
    __syncthreads();

    int tm = (tid >> 4) * 2;
    int tn = (tid & 15) * 4;
    float c0[4] = {0.f, 0.f, 0.f, 0.f};
    float c1r[4] = {0.f, 0.f, 0.f, 0.f};
#pragma unroll 8
    for (int k = 0; k < KPER; k++) {
        float a0 = As[tm][k], a1 = As[tm + 1][k];
        float4 bv = *(const float4*)&Bs[k][tn];
        c0[0] += a0 * bv.x; c0[1] += a0 * bv.y; c0[2] += a0 * bv.z; c0[3] += a0 * bv.w;
        c1r[0] += a1 * bv.x; c1r[1] += a1 * bv.y; c1r[2] += a1 * bv.z; c1r[3] += a1 * bv.w;
    }
    float* P = g_part[ks];
    *(float4*)&P[(m0 + tm) * NG + n0 + tn]     = make_float4(c0[0], c0[1], c0[2], c0[3]);
    *(float4*)&P[(m0 + tm + 1) * NG + n0 + tn] = make_float4(c1r[0], c1r[1], c1r[2], c1r[3]);
}

// ---------------- launch 2: reduce split-K + LSTM activations ----------------
__device__ __forceinline__ float sigf(float x) { return 1.f / (1.f + __expf(-x)); }

__global__ void act_kernel(const float* __restrict__ sc1,
                           const float* __restrict__ bih, const float* __restrict__ bhh,
                           float* __restrict__ dout) {
    int i = blockIdx.x * blockDim.x + threadIdx.x;
    if (i >= B_ * O_) return;
    int b = i >> 7, o = i & 127;
    float g4[4];
#pragma unroll
    for (int gi = 0; gi < 4; gi++) {
        int n = gi * O_ + o;
        float v = bih[n] + bhh[n];
#pragma unroll
        for (int ks = 0; ks < KSPL; ks++) v += g_part[ks][b * NG + n];
        g4[gi] = v;
    }
    float sc = sigf(g4[1]) * sc1[i] + sigf(g4[0]) * tanhf(g4[2]);
    float sh = sigf(g4[3]) * tanhf(sc);
    dout[OUT_OFF_SC + i] = sc;
    dout[OUT_OFF_SH + i] = sh;
}

// ---------------- attention group body (R2 ordering: k, dot, shfl, THEN v) ----------------
template <bool FULL>
__device__ __forceinline__ void attn_group(const float4* __restrict__ hk4,
                                           const float4* __restrict__ hv4,
                                           int t, int len, float4 q, int lane,
                                           float& m, float& r, float4& acc) {
    int b0 = t * (O_ / 4);
    float4 k0 = hk4[b0 + lane];
    float4 k1 = hk4[b0 + 32 + lane];
    float4 k2 = hk4[b0 + 64 + lane];
    float4 k3 = hk4[b0 + 96 + lane];
    float d0 = k0.x * q.x + k0.y * q.y + k0.z * q.z + k0.w * q.w;
    float d1 = k1.x * q.x + k1.y * q.y + k1.z * q.z + k1.w * q.w;
    float d2 = k2.x * q.x + k2.y * q.y + k2.z * q.z + k2.w * q.w;
    float d3 = k3.x * q.x + k3.y * q.y + k3.z * q.z + k3.w * q.w;
#pragma unroll
    for (int off = 16; off; off >>= 1) {
        d0 += __shfl_xor_sync(0xffffffffu, d0, off);
        d1 += __shfl_xor_sync(0xffffffffu, d1, off);
        d2 += __shfl_xor_sync(0xffffffffu, d2, off);
        d3 += __shfl_xor_sync(0xffffffffu, d3, off);
    }
    if (!FULL) {
        d1 = (t + 1 < len) ? d1 : -INFINITY;
        d2 = (t + 2 < len) ? d2 : -INFINITY;
        d3 = (t + 3 < len) ? d3 : -INFINITY;
    }
    float g = fmaxf(fmaxf(d0, d1), fmaxf(d2, d3));
    float nm = fmaxf(m, g);
    float e0 = __expf(d0 - nm);
    float e1 = __expf(d1 - nm);
    float e2 = __expf(d2 - nm);
    float e3 = __expf(d3 - nm);
    float scale = __expf(m - nm);
    float4 v0 = hv4[b0 + lane];
    float4 v1 = hv4[b0 + 32 + lane];
    float4 v2 = hv4[b0 + 64 + lane];
    float4 v3 = hv4[b0 + 96 + lane];
    acc.x = acc.x * scale + e0 * v0.x + e1 * v1.x + e2 * v2.x + e3 * v3.x;
    acc.y = acc.y * scale + e0 * v0.y + e1 * v1.y + e2 * v2.y + e3 * v3.y;
    acc.z = acc.z * scale + e0 * v0.z + e1 * v1.z + e2 * v2.z + e3 * v3.z;
    acc.w = acc.w * scale + e0 * v0.w + e1 * v1.w + e2 * v2.w + e3 * v3.w;
    r = r * scale + (e0 + e1 + e2 + e3);
    m = nm;
}

// ---------------- launch 3: attention partials (R2 structure + len skip) ----------------
__global__ void attn_partial(const float* __restrict__ hk, const float* __restrict__ hv,
                             const float* __restrict__ dout) {
    __shared__ float s_m[8], s_r[8];
    __shared__ float s_acc[8][O_];
    int b = blockIdx.y;
    int chunk = blockIdx.x;
    int tid = threadIdx.x;
    int warp = tid >> 5, lane = tid & 31;

    float4 q = ((const float4*)(dout + OUT_OFF_SC + b * O_))[lane];
    const float4* hk4 = (const float4*)(hk) + (size_t)b * T_ * (O_ / 4);
    const float4* hv4 = (const float4*)(hv) + (size_t)b * T_ * (O_ / 4);

    int len = g_len[b];
    int t0 = chunk * TCH + warp * 32;
    int v = len - t0;

    float m = -INFINITY, r = 0.f;
    float4 acc = make_float4(0.f, 0.f, 0.f, 0.f);

    if (v >= 32) {
#pragma unroll 2
        for (int i = 0; i < 32; i += 4)
            attn_group<true>(hk4, hv4, t0 + i, len, q, lane, m, r, acc);
    } else if (v > 0) {
        for (int i = 0; i < v; i += 4)
            attn_group<false>(hk4, hv4, t0 + i, len, q, lane, m, r, acc);
    }

    s_acc[warp][4 * lane + 0] = acc.x;
    s_acc[warp][4 * lane + 1] = acc.y;
    s_acc[warp][4 * lane + 2] = acc.z;
    s_acc[warp][4 * lane + 3] = acc.w;
    if (lane == 0) { s_m[warp] = m; s_r[warp] = r; }
    __syncthreads();

    if (tid < O_) {
        float M = -INFINITY;
#pragma unroll
        for (int w = 0; w < 8; w++) if (s_r[w] > 0.f) M = fmaxf(M, s_m[w]);
        float R = 0.f, A = 0.f;
#pragma unroll
        for (int w = 0; w < 8; w++) {
            if (s_r[w] > 0.f) {
                float f = __expf(s_m[w] - M);
                R += s_r[w] * f;
                A += s_acc[w][tid] * f;
            }
        }
        int p = b * SCH + chunk;
        g_pacc[p * O_ + tid] = A;
        if (tid == 0) { g_pm[p] = M; g_pr[p] = R; }
    }
}

// ---------------- launch 4: combine partials -> c, MLP + softmax ----------------
__global__ void final_kernel(const float* __restrict__ W1, const float* __restrict__ b1,
                             const float* __restrict__ W2, const float* __restrict__ b2,
                             const float* __restrict__ W3, const float* __restrict__ b3,
                             float* __restrict__ dout) {
    __shared__ float shs[O_], cs[O_], h[L_], z[L_];
    __shared__ float sM, sZ;
    int b = blockIdx.x;
    int tid = threadIdx.x;   // 128

    if (tid == 0) {
        float M = -INFINITY;
        for (int s = 0; s < SCH; s++) if (g_pr[b * SCH + s] > 0.f) M = fmaxf(M, g_pm[b * SCH + s]);
        float Z = 0.f;
        for (int s = 0; s < SCH; s++)
            if (g_pr[b * SCH + s] > 0.f) Z += g_pr[b * SCH + s] * __expf(g_pm[b * SCH + s] - M);
        sM = M; sZ = Z;
    }
    shs[tid] = dout[OUT_OFF_SH + b * O_ + tid];
    __syncthreads();
    float A = 0.f;
#pragma unroll
    for (int s = 0; s < SCH; s++) {
        if (g_pr[b * SCH + s] > 0.f)
            A += g_pacc[(b * SCH + s) * O_ + tid] * __expf(g_pm[b * SCH + s] - sM);
    }
    float cval = A / sZ;
    cs[tid] = cval;
    dout[OUT_OFF_C + b * O_ + tid] = cval;
    __syncthreads();

    if (tid < L_) {
        float a = b1[tid] + b2[tid];
        const float* w1 = &W1[tid * O_];
        const float* w2 = &W2[tid * O_];
#pragma unroll 4
        for (int k = 0; k < O_; k++) a += shs[k] * w1[k] + cs[k] * w2[k];
        h[tid] = fmaxf(a, 0.f);
    }
    __syncthreads();
    if (tid < L_) {
        float a = b3[tid];
        const float* w3 = &W3[tid * L_];
#pragma unroll
        for (int j = 0; j < L_; j++) a += h[j] * w3[j];
        z[tid] = a;
    }
    __syncthreads();
    if (tid == 0) {
        float M = -INFINITY;
        for (int j = 0; j < L_; j++) M = fmaxf(M, z[j]);
        float S = 0.f;
        for (int j = 0; j < L_; j++) { float e = __expf(z[j] - M); z[j] = e; S += e; }
        float inv = 1.f / S;
        for (int j = 0; j < L_; j++) dout[b * L_ + j] = z[j] * inv;
    }
}

// ---------------- launcher ----------------
extern "C" void kernel_launch(void* const* d_in, const int* in_sizes, int n_in,
                              void* d_out, int out_size) {
    const float* P[17];
    if (n_in >= 17 && in_sizes[0] == B_ * T_ * O_) {
        for (int i = 0; i < 17; i++) P[i] = (const float*)d_in[i];
    } else {
        P[0]  = (const float*)d_in[11];  // hk
        P[1]  = (const float*)d_in[12];  // hv
        P[2]  = (const float*)d_in[16];  // y_1
        P[3]  = (const float*)d_in[10];  // c_1
        P[4]  = (const float*)d_in[15];  // sh_1
        P[5]  = (const float*)d_in[14];  // sc_1
        P[6]  = (const float*)d_in[13];  // mask
        P[7]  = (const float*)d_in[4];   // W_ih
        P[8]  = (const float*)d_in[9];   // b_ih
        P[9]  = (const float*)d_in[3];   // W_hh
        P[10] = (const float*)d_in[8];   // b_hh
        P[11] = (const float*)d_in[0];   // W1
        P[12] = (const float*)d_in[5];   // b1
        P[13] = (const float*)d_in[1];   // W2
        P[14] = (const float*)d_in[6];   // b2
        P[15] = (const float*)d_in[2];   // W3
        P[16] = (const float*)d_in[7];   // b3
    }
    const float *hk = P[0], *hv = P[1], *y1 = P[2], *c1 = P[3], *sh1 = P[4], *sc1 = P[5];
    const float *mask = P[6], *Wih = P[7], *bih = P[8], *Whh = P[9], *bhh = P[10];
    const float *W1 = P[11], *b1 = P[12], *W2 = P[13], *b2 = P[14], *W3 = P[15], *b3 = P[16];
    float* dout = (float*)d_out;

    gemm_len_kernel<<<N_GEMM_BLK + B_, 256>>>(y1, c1, sh1, Wih, Whh, mask);
    act_kernel<<<(B_ * O_ + 255) / 256, 256>>>(sc1, bih, bhh, dout);
    attn_partial<<<dim3(SCH, B_), 256>>>(hk, hv, dout);
    final_kernel<<<B_, O_>>>(W1, b1, W2, b2, W3, b3, dout);
}

// round 8
// speedup vs baseline: 1.3106x; 1.1213x over previous
#include <cuda_runtime.h>
#include <math.h>

#define B_   128
#define T_   2048
#define O_   128
#define E_   512
#define L_   34
#define NG   512
#define KSPL 12           // 12 segment-uniform K-slabs of 64
#define KPER 64
#define BM_G 32
#define BN_G 64
#define SCH  8
#define TCH  (T_ / SCH)   // 256

// d_out layout: out[128*34] | c[128*128] | sh[128*128] | sc[128*128]
#define OUT_OFF_C   (B_ * L_)
#define OUT_OFF_SH  (OUT_OFF_C + B_ * O_)
#define OUT_OFF_SC  (OUT_OFF_SH + B_ * O_)

// ---------------- device scratch ----------------
__device__ __align__(16) float g_part[KSPL][B_ * NG];
__device__ int   g_len[B_];
__device__ float g_pm[B_ * SCH];
__device__ float g_pr[B_ * SCH];
__device__ __align__(16) float g_pacc[B_ * SCH * O_];

#define N_GEMM_BLK ((B_ / BM_G) * (NG / BN_G) * KSPL)   // 4*8*12 = 384

// ---------------- launch 1: single-shot split-K GEMM + len ----------------
__global__ void __launch_bounds__(256)
gemm_len_kernel(const float* __restrict__ y1, const float* __restrict__ c1,
                const float* __restrict__ sh1,
                const float* __restrict__ Wih, const float* __restrict__ Whh,
                const float* __restrict__ mask) {
    __shared__ float As[BM_G][68];        // [m][k]
    __shared__ float Bs[KPER][BN_G + 4];  // [k][n]
    int bid = blockIdx.x;
    int tid = threadIdx.x;

    if (bid >= N_GEMM_BLK) {
        // ---- length path ----
        float* s = &As[0][0];
        int b = bid - N_GEMM_BLK;
        int lane = tid & 31, warp = tid >> 5;
        const float4* m4 = (const float4*)(mask + (size_t)b * T_);
        float acc = 0.f;
        for (int i = tid; i < T_ / 4; i += 256) {
            float4 v = m4[i];
            acc += v.x + v.y + v.z + v.w;
        }
#pragma unroll
        for (int off = 16; off; off >>= 1) acc += __shfl_xor_sync(0xffffffffu, acc, off);
        if (lane == 0) s[warp] = acc;
        __syncthreads();
        if (tid == 0) {
            float t = 0.f;
            for (int w = 0; w < 8; w++) t += s[w];
            g_len[b] = (int)(t + 0.5f);
        }
        return;
    }

    // ---- gemm path: one K-slab, no inner syncs ----
    int ks = bid >> 5;
    int rem = bid & 31;
    int m0 = (rem >> 3) * BM_G;
    int n0 = (rem & 7) * BN_G;
    int k0 = ks * KPER;                   // segment-uniform

    const float* xbase; int xstride;
    if (k0 < E_)            { xbase = y1  + k0;             xstride = E_; }
    else if (k0 < E_ + O_)  { xbase = c1  + (k0 - E_);      xstride = O_; }
    else                    { xbase = sh1 + (k0 - E_ - O_); xstride = O_; }
    const float* wbase; int wstride;
    if (k0 < E_ + O_) { wbase = Wih + k0;             wstride = E_ + O_; }
    else              { wbase = Whh + (k0 - E_ - O_); wstride = O_; }

    {
        int row = tid >> 3, kc = (tid & 7) * 4;
        const float* ap = xbase + (size_t)(m0 + row) * xstride + kc;
        float4 a0 = *(const float4*)ap;
        float4 a1 = *(const float4*)(ap + 32);
        *(float4*)&As[row][kc]      = a0;
        *(float4*)&As[row][kc + 32] = a1;
    }
    {
        int n = tid >> 2, kc = (tid & 3) * 16;
        const float* bp = wbase + (size_t)(n0 + n) * wstride + kc;
        float4 w0 = *(const float4*)bp;
        float4 w1 = *(const float4*)(bp + 4);
        float4 w2 = *(const float4*)(bp + 8);
        float4 w3 = *(const float4*)(bp + 12);
        Bs[kc + 0][n] = w0.x;  Bs[kc + 1][n] = w0.y;  Bs[kc + 2][n] = w0.z;  Bs[kc + 3][n] = w0.w;
        Bs[kc + 4][n] = w1.x;  Bs[kc + 5][n] = w1.y;  Bs[kc + 6][n] = w1.z;  Bs[kc + 7][n] = w1.w;
        Bs[kc + 8][n] = w2.x;  Bs[kc + 9][n] = w2.y;  Bs[kc + 10][n] = w2.z; Bs[kc + 11][n] = w2.w;
        Bs[kc + 12][n] = w3.x; Bs[kc + 13][n] = w3.y; Bs[kc + 14][n] = w3.z; Bs[kc + 15][n] = w3.w;
    }
    __syncthreads();

    int tm = (tid >> 4) * 2;
    int tn = (tid & 15) * 4;
    float c0[4] = {0.f, 0.f, 0.f, 0.f};
    float c1r[4] = {0.f, 0.f, 0.f, 0.f};
#pragma unroll 8
    for (int k = 0; k < KPER; k++) {
        float a0 = As[tm][k], a1 = As[tm + 1][k];
        float4 bv = *(const float4*)&Bs[k][tn];
        c0[0] += a0 * bv.x; c0[1] += a0 * bv.y; c0[2] += a0 * bv.z; c0[3] += a0 * bv.w;
        c1r[0] += a1 * bv.x; c1r[1] += a1 * bv.y; c1r[2] += a1 * bv.z; c1r[3] += a1 * bv.w;
    }
    float* P = g_part[ks];
    *(float4*)&P[(m0 + tm) * NG + n0 + tn]     = make_float4(c0[0], c0[1], c0[2], c0[3]);
    *(float4*)&P[(m0 + tm + 1) * NG + n0 + tn] = make_float4(c1r[0], c1r[1], c1r[2], c1r[3]);
}

// ---------------- launch 2: reduce split-K + LSTM activations ----------------
__device__ __forceinline__ float sigf(float x) { return 1.f / (1.f + __expf(-x)); }

__global__ void act_kernel(const float* __restrict__ sc1,
                           const float* __restrict__ bih, const float* __restrict__ bhh,
                           float* __restrict__ dout) {
    int i = blockIdx.x * blockDim.x + threadIdx.x;
    if (i >= B_ * O_) return;
    int b = i >> 7, o = i & 127;
    float g4[4];
#pragma unroll
    for (int gi = 0; gi < 4; gi++) {
        int n = gi * O_ + o;
        float v = bih[n] + bhh[n];
#pragma unroll
        for (int ks = 0; ks < KSPL; ks++) v += g_part[ks][b * NG + n];
        g4[gi] = v;
    }
    float sc = sigf(g4[1]) * sc1[i] + sigf(g4[0]) * tanhf(g4[2]);
    float sh = sigf(g4[3]) * tanhf(sc);
    dout[OUT_OFF_SC + i] = sc;
    dout[OUT_OFF_SH + i] = sh;
}

// ---------------- attention group body (R2 ordering) ----------------
template <bool FULL>
__device__ __forceinline__ void attn_group(const float4* __restrict__ hk4,
                                           const float4* __restrict__ hv4,
                                           int t, int len, float4 q, int lane,
                                           float& m, float& r, float4& acc) {
    int b0 = t * (O_ / 4);
    float4 k0 = hk4[b0 + lane];
    float4 k1 = hk4[b0 + 32 + lane];
    float4 k2 = hk4[b0 + 64 + lane];
    float4 k3 = hk4[b0 + 96 + lane];
    float d0 = k0.x * q.x + k0.y * q.y + k0.z * q.z + k0.w * q.w;
    float d1 = k1.x * q.x + k1.y * q.y + k1.z * q.z + k1.w * q.w;
    float d2 = k2.x * q.x + k2.y * q.y + k2.z * q.z + k2.w * q.w;
    float d3 = k3.x * q.x + k3.y * q.y + k3.z * q.z + k3.w * q.w;
#pragma unroll
    for (int off = 16; off; off >>= 1) {
        d0 += __shfl_xor_sync(0xffffffffu, d0, off);
        d1 += __shfl_xor_sync(0xffffffffu, d1, off);
        d2 += __shfl_xor_sync(0xffffffffu, d2, off);
        d3 += __shfl_xor_sync(0xffffffffu, d3, off);
    }
    if (!FULL) {
        d1 = (t + 1 < len) ? d1 : -INFINITY;
        d2 = (t + 2 < len) ? d2 : -INFINITY;
        d3 = (t + 3 < len) ? d3 : -INFINITY;
    }
    float g = fmaxf(fmaxf(d0, d1), fmaxf(d2, d3));
    float nm = fmaxf(m, g);
    float e0 = __expf(d0 - nm);
    float e1 = __expf(d1 - nm);
    float e2 = __expf(d2 - nm);
    float e3 = __expf(d3 - nm);
    float scale = __expf(m - nm);
    float4 v0 = hv4[b0 + lane];
    float4 v1 = hv4[b0 + 32 + lane];
    float4 v2 = hv4[b0 + 64 + lane];
    float4 v3 = hv4[b0 + 96 + lane];
    acc.x = acc.x * scale + e0 * v0.x + e1 * v1.x + e2 * v2.x + e3 * v3.x;
    acc.y = acc.y * scale + e0 * v0.y + e1 * v1.y + e2 * v2.y + e3 * v3.y;
    acc.z = acc.z * scale + e0 * v0.z + e1 * v1.z + e2 * v2.z + e3 * v3.z;
    acc.w = acc.w * scale + e0 * v0.w + e1 * v1.w + e2 * v2.w + e3 * v3.w;
    r = r * scale + (e0 + e1 + e2 + e3);
    m = nm;
}

// ---------------- launch 3: attention partials ----------------
__global__ void attn_partial(const float* __restrict__ hk, const float* __restrict__ hv,
                             const float* __restrict__ dout) {
    __shared__ float s_m[8], s_r[8];
    __shared__ float s_acc[8][O_];
    int b = blockIdx.y;
    int chunk = blockIdx.x;
    int tid = threadIdx.x;
    int warp = tid >> 5, lane = tid & 31;

    float4 q = ((const float4*)(dout + OUT_OFF_SC + b * O_))[lane];
    const float4* hk4 = (const float4*)(hk) + (size_t)b * T_ * (O_ / 4);
    const float4* hv4 = (const float4*)(hv) + (size_t)b * T_ * (O_ / 4);

    int len = g_len[b];
    int t0 = chunk * TCH + warp * 32;
    int v = len - t0;

    float m = -INFINITY, r = 0.f;
    float4 acc = make_float4(0.f, 0.f, 0.f, 0.f);

    if (v >= 32) {
#pragma unroll 2
        for (int i = 0; i < 32; i += 4)
            attn_group<true>(hk4, hv4, t0 + i, len, q, lane, m, r, acc);
    } else if (v > 0) {
        for (int i = 0; i < v; i += 4)
            attn_group<false>(hk4, hv4, t0 + i, len, q, lane, m, r, acc);
    }

    s_acc[warp][4 * lane + 0] = acc.x;
    s_acc[warp][4 * lane + 1] = acc.y;
    s_acc[warp][4 * lane + 2] = acc.z;
    s_acc[warp][4 * lane + 3] = acc.w;
    if (lane == 0) { s_m[warp] = m; s_r[warp] = r; }
    __syncthreads();

    if (tid < O_) {
        float M = -INFINITY;
#pragma unroll
        for (int w = 0; w < 8; w++) if (s_r[w] > 0.f) M = fmaxf(M, s_m[w]);
        float R = 0.f, A = 0.f;
#pragma unroll
        for (int w = 0; w < 8; w++) {
            if (s_r[w] > 0.f) {
                float f = __expf(s_m[w] - M);
                R += s_r[w] * f;
                A += s_acc[w][tid] * f;
            }
        }
        int p = b * SCH + chunk;
        g_pacc[p * O_ + tid] = A;
        if (tid == 0) { g_pm[p] = M; g_pr[p] = R; }
    }
}

// ---------------- launch 4: combine -> c, warp-parallel MLP + softmax ----------------
__global__ void __launch_bounds__(256)
final_kernel(const float* __restrict__ W1, const float* __restrict__ b1,
             const float* __restrict__ W2, const float* __restrict__ b2,
             const float* __restrict__ W3, const float* __restrict__ b3,
             float* __restrict__ dout) {
    __shared__ __align__(16) float shs[O_], cs[O_];
    __shared__ float h[L_], z[L_];
    __shared__ float sM, sZ;
    int b = blockIdx.x;
    int tid = threadIdx.x;      // 256
    int warp = tid >> 5, lane = tid & 31;

    if (tid == 0) {
        float M = -INFINITY;
        for (int s = 0; s < SCH; s++) if (g_pr[b * SCH + s] > 0.f) M = fmaxf(M, g_pm[b * SCH + s]);
        float Z = 0.f;
        for (int s = 0; s < SCH; s++)
            if (g_pr[b * SCH + s] > 0.f) Z += g_pr[b * SCH + s] * __expf(g_pm[b * SCH + s] - M);
        sM = M; sZ = Z;
    }
    if (tid < O_) shs[tid] = dout[OUT_OFF_SH + b * O_ + tid];
    __syncthreads();

    if (tid < O_) {
        float A = 0.f;
#pragma unroll
        for (int s = 0; s < SCH; s++) {
            if (g_pr[b * SCH + s] > 0.f)
                A += g_pacc[(b * SCH + s) * O_ + tid] * __expf(g_pm[b * SCH + s] - sM);
        }
        float cval = A / sZ;
        cs[tid] = cval;
        dout[OUT_OFF_C + b * O_ + tid] = cval;
    }
    __syncthreads();

    // ---- layer 1: warp-per-output, lane = float4 k-chunk (coalesced 128B/warp) ----
#pragma unroll
    for (int r = 0; r < 5; r++) {
        int j = r * 8 + warp;          // 0..39
        if (j < L_) {
            float4 w1 = ((const float4*)(W1 + j * O_))[lane];
            float4 w2 = ((const float4*)(W2 + j * O_))[lane];
            float4 s4 = *(const float4*)&shs[lane * 4];
            float4 c4 = *(const float4*)&cs[lane * 4];
            float a = w1.x * s4.x + w1.y * s4.y + w1.z * s4.z + w1.w * s4.w
                    + w2.x * c4.x + w2.y * c4.y + w2.z * c4.z + w2.w * c4.w;
#pragma unroll
            for (int off = 16; off; off >>= 1) a += __shfl_xor_sync(0xffffffffu, a, off);
            if (lane == 0) h[j] = fmaxf(a + b1[j] + b2[j], 0.f);
        }
    }
    __syncthreads();

    // ---- layer 2: warp-per-output, lane = k (34 values: lane + tail lanes 0,1) ----
#pragma unroll
    for (int r = 0; r < 5; r++) {
        int j = r * 8 + warp;
        if (j < L_) {
            const float* w3 = W3 + j * L_;
            float a = h[lane] * w3[lane];   // lane 0..31 (h[32..33] handled below)
            if (lane < 2) a += h[lane + 32] * w3[lane + 32];
#pragma unroll
            for (int off = 16; off; off >>= 1) a += __shfl_xor_sync(0xffffffffu, a, off);
            if (lane == 0) z[j] = a + b3[j];
        }
    }
    __syncthreads();

    // ---- softmax over 34 by warp 0 ----
    if (warp == 0) {
        float v0 = z[lane];
        float v1 = (lane < 2) ? z[lane + 32] : -INFINITY;
        float mx = fmaxf(v0, v1);
#pragma unroll
        for (int off = 16; off; off >>= 1) mx = fmaxf(mx, __shfl_xor_sync(0xffffffffu, mx, off));
        float e0 = __expf(v0 - mx);
        float e1 = (lane < 2) ? __expf(v1 - mx) : 0.f;
        float s = e0 + e1;
#pragma unroll
        for (int off = 16; off; off >>= 1) s += __shfl_xor_sync(0xffffffffu, s, off);
        float inv = 1.f / s;
        dout[b * L_ + lane] = e0 * inv;
        if (lane < 2) dout[b * L_ + lane + 32] = e1 * inv;
    }
}

// ---------------- launcher ----------------
extern "C" void kernel_launch(void* const* d_in, const int* in_sizes, int n_in,
                              void* d_out, int out_size) {
    const float* P[17];
    if (n_in >= 17 && in_sizes[0] == B_ * T_ * O_) {
        for (int i = 0; i < 17; i++) P[i] = (const float*)d_in[i];
    } else {
        P[0]  = (const float*)d_in[11];  // hk
        P[1]  = (const float*)d_in[12];  // hv
        P[2]  = (const float*)d_in[16];  // y_1
        P[3]  = (const float*)d_in[10];  // c_1
        P[4]  = (const float*)d_in[15];  // sh_1
        P[5]  = (const float*)d_in[14];  // sc_1
        P[6]  = (const float*)d_in[13];  // mask
        P[7]  = (const float*)d_in[4];   // W_ih
        P[8]  = (const float*)d_in[9];   // b_ih
        P[9]  = (const float*)d_in[3];   // W_hh
        P[10] = (const float*)d_in[8];   // b_hh
        P[11] = (const float*)d_in[0];   // W1
        P[12] = (const float*)d_in[5];   // b1
        P[13] = (const float*)d_in[1];   // W2
        P[14] = (const float*)d_in[6];   // b2
        P[15] = (const float*)d_in[2];   // W3
        P[16] = (const float*)d_in[7];   // b3
    }
    const float *hk = P[0], *hv = P[1], *y1 = P[2], *c1 = P[3], *sh1 = P[4], *sc1 = P[5];
    const float *mask = P[6], *Wih = P[7], *bih = P[8], *Whh = P[9], *bhh = P[10];
    const float *W1 = P[11], *b1 = P[12], *W2 = P[13], *b2 = P[14], *W3 = P[15], *b3 = P[16];
    float* dout = (float*)d_out;

    gemm_len_kernel<<<N_GEMM_BLK + B_, 256>>>(y1, c1, sh1, Wih, Whh, mask);
    act_kernel<<<(B_ * O_ + 255) / 256, 256>>>(sc1, bih, bhh, dout);
    attn_partial<<<dim3(SCH, B_), 256>>>(hk, hv, dout);
    final_kernel<<<B_, 256>>>(W1, b1, W2, b2, W3, b3, dout);
}

// round 9
// speedup vs baseline: 1.4685x; 1.1204x over previous
#include <cuda_runtime.h>
#include <math.h>

#define B_   128
#define T_   2048
#define O_   128
#define E_   512
#define L_   34
#define NG   512
#define KSPL 12           // 12 segment-uniform K-slabs of 64
#define KPER 64
#define BM_G 32
#define BN_G 64
#define SCH  8
#define TCH  (T_ / SCH)   // 256

// d_out layout: out[128*34] | c[128*128] | sh[128*128] | sc[128*128]
#define OUT_OFF_C   (B_ * L_)
#define OUT_OFF_SH  (OUT_OFF_C + B_ * O_)
#define OUT_OFF_SC  (OUT_OFF_SH + B_ * O_)

// ---------------- device scratch ----------------
__device__ __align__(16) float g_part[KSPL][B_ * NG];
__device__ int   g_len[B_];
__device__ float g_pm[B_ * SCH];
__device__ float g_pr[B_ * SCH];
__device__ __align__(16) float g_pacc[B_ * SCH * O_];
__device__ int   g_cnt[B_];   // zero-init; self-resetting ticket

#define N_GEMM_BLK ((B_ / BM_G) * (NG / BN_G) * KSPL)   // 4*8*12 = 384

// ---------------- launch 1: single-shot split-K GEMM + len ----------------
__global__ void __launch_bounds__(256)
gemm_len_kernel(const float* __restrict__ y1, const float* __restrict__ c1,
                const float* __restrict__ sh1,
                const float* __restrict__ Wih, const float* __restrict__ Whh,
                const float* __restrict__ mask) {
    __shared__ float As[BM_G][68];        // [m][k]
    __shared__ float Bs[KPER][BN_G + 4];  // [k][n]
    int bid = blockIdx.x;
    int tid = threadIdx.x;

    if (bid >= N_GEMM_BLK) {
        // ---- length path ----
        float* s = &As[0][0];
        int b = bid - N_GEMM_BLK;
        int lane = tid & 31, warp = tid >> 5;
        const float4* m4 = (const float4*)(mask + (size_t)b * T_);
        float acc = 0.f;
        for (int i = tid; i < T_ / 4; i += 256) {
            float4 v = m4[i];
            acc += v.x + v.y + v.z + v.w;
        }
#pragma unroll
        for (int off = 16; off; off >>= 1) acc += __shfl_xor_sync(0xffffffffu, acc, off);
        if (lane == 0) s[warp] = acc;
        __syncthreads();
        if (tid == 0) {
            float t = 0.f;
            for (int w = 0; w < 8; w++) t += s[w];
            g_len[b] = (int)(t + 0.5f);
        }
        return;
    }

    // ---- gemm path: one K-slab, no inner syncs ----
    int ks = bid >> 5;
    int rem = bid & 31;
    int m0 = (rem >> 3) * BM_G;
    int n0 = (rem & 7) * BN_G;
    int k0 = ks * KPER;                   // segment-uniform

    const float* xbase; int xstride;
    if (k0 < E_)            { xbase = y1  + k0;             xstride = E_; }
    else if (k0 < E_ + O_)  { xbase = c1  + (k0 - E_);      xstride = O_; }
    else                    { xbase = sh1 + (k0 - E_ - O_); xstride = O_; }
    const float* wbase; int wstride;
    if (k0 < E_ + O_) { wbase = Wih + k0;             wstride = E_ + O_; }
    else              { wbase = Whh + (k0 - E_ - O_); wstride = O_; }

    {
        int row = tid >> 3, kc = (tid & 7) * 4;
        const float* ap = xbase + (size_t)(m0 + row) * xstride + kc;
        float4 a0 = *(const float4*)ap;
        float4 a1 = *(const float4*)(ap + 32);
        *(float4*)&As[row][kc]      = a0;
        *(float4*)&As[row][kc + 32] = a1;
    }
    {
        int n = tid >> 2, kc = (tid & 3) * 16;
        const float* bp = wbase + (size_t)(n0 + n) * wstride + kc;
        float4 w0 = *(const float4*)bp;
        float4 w1 = *(const float4*)(bp + 4);
        float4 w2 = *(const float4*)(bp + 8);
        float4 w3 = *(const float4*)(bp + 12);
        Bs[kc + 0][n] = w0.x;  Bs[kc + 1][n] = w0.y;  Bs[kc + 2][n] = w0.z;  Bs[kc + 3][n] = w0.w;
        Bs[kc + 4][n] = w1.x;  Bs[kc + 5][n] = w1.y;  Bs[kc + 6][n] = w1.z;  Bs[kc + 7][n] = w1.w;
        Bs[kc + 8][n] = w2.x;  Bs[kc + 9][n] = w2.y;  Bs[kc + 10][n] = w2.z; Bs[kc + 11][n] = w2.w;
        Bs[kc + 12][n] = w3.x; Bs[kc + 13][n] = w3.y; Bs[kc + 14][n] = w3.z; Bs[kc + 15][n] = w3.w;
    }
    __syncthreads();

    int tm = (tid >> 4) * 2;
    int tn = (tid & 15) * 4;
    float c0[4] = {0.f, 0.f, 0.f, 0.f};
    float c1r[4] = {0.f, 0.f, 0.f, 0.f};
#pragma unroll 8
    for (int k = 0; k < KPER; k++) {
        float a0 = As[tm][k], a1 = As[tm + 1][k];
        float4 bv = *(const float4*)&Bs[k][tn];
        c0[0] += a0 * bv.x; c0[1] += a0 * bv.y; c0[2] += a0 * bv.z; c0[3] += a0 * bv.w;
        c1r[0] += a1 * bv.x; c1r[1] += a1 * bv.y; c1r[2] += a1 * bv.z; c1r[3] += a1 * bv.w;
    }
    float* P = g_part[ks];
    *(float4*)&P[(m0 + tm) * NG + n0 + tn]     = make_float4(c0[0], c0[1], c0[2], c0[3]);
    *(float4*)&P[(m0 + tm + 1) * NG + n0 + tn] = make_float4(c1r[0], c1r[1], c1r[2], c1r[3]);
}

// ---------------- attention group body (R2 ordering: k, dot, shfl, THEN v) ----------------
__device__ __forceinline__ float sigf(float x) { return 1.f / (1.f + __expf(-x)); }

template <bool FULL>
__device__ __forceinline__ void attn_group(const float4* __restrict__ hk4,
                                           const float4* __restrict__ hv4,
                                           int t, int len, float4 q, int lane,
                                           float& m, float& r, float4& acc) {
    int b0 = t * (O_ / 4);
    float4 k0 = hk4[b0 + lane];
    float4 k1 = hk4[b0 + 32 + lane];
    float4 k2 = hk4[b0 + 64 + lane];
    float4 k3 = hk4[b0 + 96 + lane];
    float d0 = k0.x * q.x + k0.y * q.y + k0.z * q.z + k0.w * q.w;
    float d1 = k1.x * q.x + k1.y * q.y + k1.z * q.z + k1.w * q.w;
    float d2 = k2.x * q.x + k2.y * q.y + k2.z * q.z + k2.w * q.w;
    float d3 = k3.x * q.x + k3.y * q.y + k3.z * q.z + k3.w * q.w;
#pragma unroll
    for (int off = 16; off; off >>= 1) {
        d0 += __shfl_xor_sync(0xffffffffu, d0, off);
        d1 += __shfl_xor_sync(0xffffffffu, d1, off);
        d2 += __shfl_xor_sync(0xffffffffu, d2, off);
        d3 += __shfl_xor_sync(0xffffffffu, d3, off);
    }
    if (!FULL) {
        d1 = (t + 1 < len) ? d1 : -INFINITY;
        d2 = (t + 2 < len) ? d2 : -INFINITY;
        d3 = (t + 3 < len) ? d3 : -INFINITY;
    }
    float g = fmaxf(fmaxf(d0, d1), fmaxf(d2, d3));
    float nm = fmaxf(m, g);
    float e0 = __expf(d0 - nm);
    float e1 = __expf(d1 - nm);
    float e2 = __expf(d2 - nm);
    float e3 = __expf(d3 - nm);
    float scale = __expf(m - nm);
    float4 v0 = hv4[b0 + lane];
    float4 v1 = hv4[b0 + 32 + lane];
    float4 v2 = hv4[b0 + 64 + lane];
    float4 v3 = hv4[b0 + 96 + lane];
    acc.x = acc.x * scale + e0 * v0.x + e1 * v1.x + e2 * v2.x + e3 * v3.x;
    acc.y = acc.y * scale + e0 * v0.y + e1 * v1.y + e2 * v2.y + e3 * v3.y;
    acc.z = acc.z * scale + e0 * v0.z + e1 * v1.z + e2 * v2.z + e3 * v3.z;
    acc.w = acc.w * scale + e0 * v0.w + e1 * v1.w + e2 * v2.w + e3 * v3.w;
    r = r * scale + (e0 + e1 + e2 + e3);
    m = nm;
}

// ---------------- launch 2: act (inline) + attention + ticketed combine/MLP ----------------
__global__ void attn_all(const float* __restrict__ hk, const float* __restrict__ hv,
                         const float* __restrict__ sc1,
                         const float* __restrict__ bih, const float* __restrict__ bhh,
                         float* __restrict__ dout,
                         const float* __restrict__ W1, const float* __restrict__ b1,
                         const float* __restrict__ W2, const float* __restrict__ b2,
                         const float* __restrict__ W3, const float* __restrict__ b3) {
    __shared__ __align__(16) float s_q[O_];    // sc
    __shared__ __align__(16) float s_sh[O_];
    __shared__ float s_m[8], s_r[8];
    __shared__ float s_acc[8][O_];
    __shared__ int s_last;
    int b = blockIdx.y;
    int chunk = blockIdx.x;
    int tid = threadIdx.x;
    int warp = tid >> 5, lane = tid & 31;

    // ---- startup: redundant per-block LSTM activations from split-K partials ----
    if (tid < O_) {
        int o = tid;
        float g4[4];
#pragma unroll
        for (int gi = 0; gi < 4; gi++) {
            int n = gi * O_ + o;
            float v = bih[n] + bhh[n];
#pragma unroll
            for (int ks = 0; ks < KSPL; ks++) v += g_part[ks][b * NG + n];
            g4[gi] = v;
        }
        float sc = sigf(g4[1]) * sc1[b * O_ + o] + sigf(g4[0]) * tanhf(g4[2]);
        float sh = sigf(g4[3]) * tanhf(sc);
        s_q[o] = sc;
        s_sh[o] = sh;
        if (chunk == 0) {
            dout[OUT_OFF_SC + b * O_ + o] = sc;
            dout[OUT_OFF_SH + b * O_ + o] = sh;
        }
    }
    __syncthreads();

    float4 q = ((const float4*)s_q)[lane];
    const float4* hk4 = (const float4*)(hk) + (size_t)b * T_ * (O_ / 4);
    const float4* hv4 = (const float4*)(hv) + (size_t)b * T_ * (O_ / 4);

    int len = g_len[b];
    int t0 = chunk * TCH + warp * 32;
    int v = len - t0;

    float m = -INFINITY, r = 0.f;
    float4 acc = make_float4(0.f, 0.f, 0.f, 0.f);

    if (v >= 32) {
#pragma unroll 2
        for (int i = 0; i < 32; i += 4)
            attn_group<true>(hk4, hv4, t0 + i, len, q, lane, m, r, acc);
    } else if (v > 0) {
        for (int i = 0; i < v; i += 4)
            attn_group<false>(hk4, hv4, t0 + i, len, q, lane, m, r, acc);
    }

    s_acc[warp][4 * lane + 0] = acc.x;
    s_acc[warp][4 * lane + 1] = acc.y;
    s_acc[warp][4 * lane + 2] = acc.z;
    s_acc[warp][4 * lane + 3] = acc.w;
    if (lane == 0) { s_m[warp] = m; s_r[warp] = r; }
    __syncthreads();

    if (tid < O_) {
        float M = -INFINITY;
#pragma unroll
        for (int w = 0; w < 8; w++) if (s_r[w] > 0.f) M = fmaxf(M, s_m[w]);
        float R = 0.f, A = 0.f;
#pragma unroll
        for (int w = 0; w < 8; w++) {
            if (s_r[w] > 0.f) {
                float f = __expf(s_m[w] - M);
                R += s_r[w] * f;
                A += s_acc[w][tid] * f;
            }
        }
        int p = b * SCH + chunk;
        g_pacc[p * O_ + tid] = A;
        if (tid == 0) { g_pm[p] = M; g_pr[p] = R; }
    }
    __syncthreads();

    // ---- ticket: last-arriving block for this batch row finishes the pipeline ----
    if (tid == 0) {
        __threadfence();
        int old = atomicAdd(&g_cnt[b], 1);
        if (old == SCH - 1) { g_cnt[b] = 0; s_last = 1; } else { s_last = 0; }
    }
    __syncthreads();
    if (!s_last) return;
    __threadfence();   // acquire: other blocks' partials visible

    // ---- combine partials -> c ----
    __shared__ __align__(16) float cs[O_];
    __shared__ float h[L_], z[L_];
    __shared__ float sM, sZ;
    if (tid == 0) {
        float M = -INFINITY;
        for (int s = 0; s < SCH; s++) if (g_pr[b * SCH + s] > 0.f) M = fmaxf(M, g_pm[b * SCH + s]);
        float Z = 0.f;
        for (int s = 0; s < SCH; s++)
            if (g_pr[b * SCH + s] > 0.f) Z += g_pr[b * SCH + s] * __expf(g_pm[b * SCH + s] - M);
        sM = M; sZ = Z;
    }
    __syncthreads();
    if (tid < O_) {
        float A = 0.f;
#pragma unroll
        for (int s = 0; s < SCH; s++) {
            if (g_pr[b * SCH + s] > 0.f)
                A += g_pacc[(b * SCH + s) * O_ + tid] * __expf(g_pm[b * SCH + s] - sM);
        }
        float cval = A / sZ;
        cs[tid] = cval;
        dout[OUT_OFF_C + b * O_ + tid] = cval;
    }
    __syncthreads();

    // ---- layer 1: warp-per-output (lane = float4 k-chunk) ----
#pragma unroll
    for (int rr = 0; rr < 5; rr++) {
        int j = rr * 8 + warp;
        if (j < L_) {
            float4 w1 = ((const float4*)(W1 + j * O_))[lane];
            float4 w2 = ((const float4*)(W2 + j * O_))[lane];
            float4 s4 = *(const float4*)&s_sh[lane * 4];
            float4 c4 = *(const float4*)&cs[lane * 4];
            float a = w1.x * s4.x + w1.y * s4.y + w1.z * s4.z + w1.w * s4.w
                    + w2.x * c4.x + w2.y * c4.y + w2.z * c4.z + w2.w * c4.w;
#pragma unroll
            for (int off = 16; off; off >>= 1) a += __shfl_xor_sync(0xffffffffu, a, off);
            if (lane == 0) h[j] = fmaxf(a + b1[j] + b2[j], 0.f);
        }
    }
    __syncthreads();

    // ---- layer 2: warp-per-output ----
#pragma unroll
    for (int rr = 0; rr < 5; rr++) {
        int j = rr * 8 + warp;
        if (j < L_) {
            const float* w3 = W3 + j * L_;
            float a = h[lane] * w3[lane];
            if (lane < 2) a += h[lane + 32] * w3[lane + 32];
#pragma unroll
            for (int off = 16; off; off >>= 1) a += __shfl_xor_sync(0xffffffffu, a, off);
            if (lane == 0) z[j] = a + b3[j];
        }
    }
    __syncthreads();

    // ---- softmax over 34 by warp 0 ----
    if (warp == 0) {
        float v0 = z[lane];
        float v1 = (lane < 2) ? z[lane + 32] : -INFINITY;
        float mx = fmaxf(v0, v1);
#pragma unroll
        for (int off = 16; off; off >>= 1) mx = fmaxf(mx, __shfl_xor_sync(0xffffffffu, mx, off));
        float e0 = __expf(v0 - mx);
        float e1 = (lane < 2) ? __expf(v1 - mx) : 0.f;
        float s = e0 + e1;
#pragma unroll
        for (int off = 16; off; off >>= 1) s += __shfl_xor_sync(0xffffffffu, s, off);
        float inv = 1.f / s;
        dout[b * L_ + lane] = e0 * inv;
        if (lane < 2) dout[b * L_ + lane + 32] = e1 * inv;
    }
}

// ---------------- launcher ----------------
extern "C" void kernel_launch(void* const* d_in, const int* in_sizes, int n_in,
                              void* d_out, int out_size) {
    const float* P[17];
    if (n_in >= 17 && in_sizes[0] == B_ * T_ * O_) {
        for (int i = 0; i < 17; i++) P[i] = (const float*)d_in[i];
    } else {
        P[0]  = (const float*)d_in[11];  // hk
        P[1]  = (const float*)d_in[12];  // hv
        P[2]  = (const float*)d_in[16];  // y_1
        P[3]  = (const float*)d_in[10];  // c_1
        P[4]  = (const float*)d_in[15];  // sh_1
        P[5]  = (const float*)d_in[14];  // sc_1
        P[6]  = (const float*)d_in[13];  // mask
        P[7]  = (const float*)d_in[4];   // W_ih
        P[8]  = (const float*)d_in[9];   // b_ih
        P[9]  = (const float*)d_in[3];   // W_hh
        P[10] = (const float*)d_in[8];   // b_hh
        P[11] = (const float*)d_in[0];   // W1
        P[12] = (const float*)d_in[5];   // b1
        P[13] = (const float*)d_in[1];   // W2
        P[14] = (const float*)d_in[6];   // b2
        P[15] = (const float*)d_in[2];   // W3
        P[16] = (const float*)d_in[7];   // b3
    }
    const float *hk = P[0], *hv = P[1], *y1 = P[2], *c1 = P[3], *sh1 = P[4], *sc1 = P[5];
    const float *mask = P[6], *Wih = P[7], *bih = P[8], *Whh = P[9], *bhh = P[10];
    const float *W1 = P[11], *b1 = P[12], *W2 = P[13], *b2 = P[14], *W3 = P[15], *b3 = P[16];
    float* dout = (float*)d_out;

    gemm_len_kernel<<<N_GEMM_BLK + B_, 256>>>(y1, c1, sh1, Wih, Whh, mask);
    attn_all<<<dim3(SCH, B_), 256>>>(hk, hv, sc1, bih, bhh, dout,
                                     W1, b1, W2, b2, W3, b3);
}